// round 13
// baseline (speedup 1.0000x reference)
#include <cuda_runtime.h>
#include <cuda_bf16.h>
#include <cstdint>

// Problem constants
#define BB 8
#define QQ 64
#define CC 512
#define DD 512
#define HH 256
#define EPSF 1e-5f
#define WOFF (BB * QQ * DD)

typedef unsigned long long ull;

__device__ float g_resq[BB * QQ * HH];        // [bq][h]
__device__ float g_rescT[BB * HH * CC];       // [b][h][c]
__device__ float g_spart[BB * QQ * 2];        // [bq][chalf] partial softmax sums

__device__ __forceinline__ float tanh_approx(float x) {
    float y;
    asm("tanh.approx.f32 %0, %1;" : "=f"(y) : "f"(x));
    return y;
}
__device__ __forceinline__ ull pack2(float x) {
    ull r; asm("mov.b64 %0, {%1, %1};" : "=l"(r) : "f"(x)); return r;
}
__device__ __forceinline__ void fma2(ull& d, ull a, ull b) {
    asm("fma.rn.f32x2 %0, %1, %2, %0;" : "+l"(d) : "l"(a), "l"(b));
}
__device__ __forceinline__ float2 unpack2(ull v) {
    float2 r; asm("mov.b64 {%0, %1}, %2;" : "=f"(r.x), "=f"(r.y) : "l"(v)); return r;
}
__device__ __forceinline__ uint32_t s2u(const void* p) {
    uint32_t a;
    asm("{ .reg .u64 t; cvta.to.shared.u64 t, %1; cvt.u32.u64 %0, t; }"
        : "=r"(a) : "l"(p));
    return a;
}
__device__ __forceinline__ void cp16(uint32_t s, const void* g) {
    asm volatile("cp.async.cg.shared.global [%0], [%1], 16;" :: "r"(s), "l"(g) : "memory");
}

#define MMA_TF32(c, a, b0, b1)                                            \
    asm volatile("mma.sync.aligned.m16n8k8.row.col.f32.tf32.tf32.f32 "    \
                 "{%0,%1,%2,%3}, {%4,%5,%6,%7}, {%8,%9}, {%0,%1,%2,%3};"  \
                 : "+f"((c)[0]), "+f"((c)[1]), "+f"((c)[2]), "+f"((c)[3]) \
                 : "r"((a)[0]), "r"((a)[1]), "r"((a)[2]), "r"((a)[3]),    \
                   "r"(b0), "r"(b1))

// ---- tc_gemms tiling: K-tile 64, 3 stages ----
#define LDA 72
#define ATILE_U (128 * LDA)
#define BTILE_U (64 * LDA)
#define STAGE_U (ATILE_U + BTILE_U)
#define NSTAGE 3
#define TCG_SMEM (NSTAGE * STAGE_U * 4)   // 165888 B

// ---------------------------------------------------------------------------
// A: tf32 mma.sync GEMMs, cp.async 3-stage pipeline, K-tile 64. 144 blocks.
// ---------------------------------------------------------------------------
__global__ __launch_bounds__(256, 1)
void tc_gemms(const float* __restrict__ Wc,
              const float* __restrict__ Ctx,
              const float* __restrict__ bc,
              const float* __restrict__ Qm,
              const float* __restrict__ Wq)
{
    extern __shared__ uint32_t smem[];
    const uint32_t smem_b = s2u(smem);

    const int tid  = threadIdx.x;
    const int wid  = tid >> 5;
    const int lane = tid & 31;
    const int g    = lane >> 2;
    const int tg   = lane & 3;

    const int mbase = (wid & 3) * 32;
    const int nbase = (wid >> 2) * 32;

    const float *Ap, *Bp;
    const float* biasp = nullptr;
    float* outp;
    int ldo;
    const int blk = blockIdx.x;
    if (blk < 128) {
        const int b  = blk >> 4;
        const int ht = (blk >> 3) & 1;
        const int ct = blk & 7;
        Ap    = Wc + (size_t)(ht * 128) * DD;
        Bp    = Ctx + (size_t)b * CC * DD + (size_t)(ct * 64) * DD;
        outp  = g_rescT + (size_t)b * HH * CC + (size_t)(ht * 128) * CC + ct * 64;
        ldo   = CC;
        biasp = bc + ht * 128;
    } else {
        const int blk2 = blk - 128;
        const int mt = blk2 >> 2;
        const int nt = blk2 & 3;
        Ap   = Qm + (size_t)(mt * 128) * DD;
        Bp   = Wq + (size_t)(nt * 64) * DD;
        outp = g_resq + (size_t)(mt * 128) * HH + nt * 64;
        ldo  = HH;
    }

    int am[8], ak[8], bm[4], bk[4];
    #pragma unroll
    for (int i = 0; i < 8; i++) {
        const int f = tid + (i << 8);
        am[i] = f >> 4;
        ak[i] = (f & 15) << 2;
    }
    #pragma unroll
    for (int i = 0; i < 4; i++) {
        const int f = tid + (i << 8);
        bm[i] = f >> 4;
        bk[i] = (f & 15) << 2;
    }

    auto issue_stage = [&](int buf, int kt) {
        const uint32_t base = smem_b + buf * (STAGE_U * 4);
        #pragma unroll
        for (int i = 0; i < 8; i++)
            cp16(base + (am[i] * LDA + ak[i]) * 4,
                 Ap + (size_t)am[i] * DD + kt + ak[i]);
        #pragma unroll
        for (int i = 0; i < 4; i++)
            cp16(base + (ATILE_U + bm[i] * LDA + bk[i]) * 4,
                 Bp + (size_t)bm[i] * DD + kt + bk[i]);
        asm volatile("cp.async.commit_group;" ::: "memory");
    };

    float acc[2][4][4] = {};

    issue_stage(0, 0);
    issue_stage(1, 64);

    const int foff = 2 * tg;

    #pragma unroll 1
    for (int t = 0; t < 8; t++) {
        if (t < 6) {
            asm volatile("cp.async.wait_group 1;" ::: "memory");
        } else {
            asm volatile("cp.async.wait_group 0;" ::: "memory");
        }
        __syncthreads();

        if (t < 6) issue_stage((t + 2) % NSTAGE, (t + 2) * 64);

        const uint32_t* A_s = smem + (t % NSTAGE) * STAGE_U;
        const uint32_t* B_s = A_s + ATILE_U;
        #pragma unroll
        for (int ks = 0; ks < 8; ks++) {
            const int kc = ks * 8 + foff;
            uint32_t a[2][4];
            #pragma unroll
            for (int mt = 0; mt < 2; mt++) {
                const int rbase = (mbase + mt * 16 + g) * LDA + kc;
                const uint2 lo = *(const uint2*)&A_s[rbase];
                const uint2 hi = *(const uint2*)&A_s[rbase + 8 * LDA];
                a[mt][0] = lo.x; a[mt][2] = lo.y;
                a[mt][1] = hi.x; a[mt][3] = hi.y;
            }
            #pragma unroll
            for (int nt = 0; nt < 4; nt++) {
                const int bbase = (nbase + nt * 8 + g) * LDA + kc;
                const uint2 bv = *(const uint2*)&B_s[bbase];
                MMA_TF32(acc[0][nt], a[0], bv.x, bv.y);
                MMA_TF32(acc[1][nt], a[1], bv.x, bv.y);
            }
        }
    }

    #pragma unroll
    for (int mt = 0; mt < 2; mt++) {
        const int row0 = mbase + mt * 16 + g;
        const int row1 = row0 + 8;
        const float bi0 = biasp ? biasp[row0] : 0.f;
        const float bi1 = biasp ? biasp[row1] : 0.f;
        #pragma unroll
        for (int nt = 0; nt < 4; nt++) {
            const int col = nbase + nt * 8 + tg * 2;
            float2 o0; o0.x = acc[mt][nt][0] + bi0; o0.y = acc[mt][nt][1] + bi0;
            float2 o1; o1.x = acc[mt][nt][2] + bi1; o1.y = acc[mt][nt][3] + bi1;
            *(float2*)(outp + (size_t)row0 * ldo + col) = o0;
            *(float2*)(outp + (size_t)row1 * ldo + col) = o1;
        }
    }
}

// ---------------------------------------------------------------------------
// B: logits -> unnormalized e. Work item = (b, q-pair, c-half of 256).
// grid 512 x 512 threads (3-4 blocks/SM: latency hidden, all SMs busy).
// Threads: c_local = tid&255, h-half = tid>>8 (partials combined in smem).
// Writes e to out[WOFF..]; per-(b,q) partial sums to g_spart (no atomics).
// ---------------------------------------------------------------------------
__global__ __launch_bounds__(512)
void logits_e(const float* __restrict__ Maskp,
              const float* __restrict__ Wo,
              const float* __restrict__ bo_p,
              float* __restrict__ out)
{
    const int blk    = blockIdx.x;       // 0..511
    const int b      = blk >> 6;
    const int rem    = blk & 63;
    const int q0     = (rem >> 1) * 2;   // q-pair
    const int chalf  = rem & 1;
    const int c0     = chalf << 8;       // 0 or 256

    const int tid  = threadIdx.x;
    const int cl   = tid & 255;
    const int hh   = tid >> 8;           // 0/1

    __shared__ float2 sh_rq[HH];
    __shared__ float  sh_wo[HH];
    __shared__ float2 sh_acc[256];
    __shared__ float  sh_part[2][8];

    if (tid < HH) {
        float2 r;
        r.x = g_resq[(b * QQ + q0 + 0) * HH + tid];
        r.y = g_resq[(b * QQ + q0 + 1) * HH + tid];
        sh_rq[tid] = r;
        sh_wo[tid] = Wo[tid];
    }
    __syncthreads();

    float a0 = 0.f, a1 = 0.f;
    {
        const int hbase = hh << 7;
        const float* rc = g_rescT + (size_t)b * HH * CC + (size_t)hbase * CC + c0 + cl;
        #pragma unroll 8
        for (int h = 0; h < 128; h++) {
            const float  a  = rc[(size_t)h * CC];
            const float2 rq = sh_rq[hbase + h];
            const float  w  = sh_wo[hbase + h];
            a0 += w * tanh_approx(a + rq.x);
            a1 += w * tanh_approx(a + rq.y);
        }
    }
    if (hh == 0) {
        sh_acc[cl] = make_float2(a0, a1);
    }
    __syncthreads();

    if (hh == 1) {
        const float2 p = sh_acc[cl];
        const float bo = __ldg(bo_p);
        const float m  = Maskp[b * CC + c0 + cl];
        const float e0 = m * __expf(a0 + p.x + bo);
        const float e1 = m * __expf(a1 + p.y + bo);

        out[WOFF + (b * QQ + q0 + 0) * CC + c0 + cl] = e0;
        out[WOFF + (b * QQ + q0 + 1) * CC + c0 + cl] = e1;

        float s0 = e0, s1 = e1;
        #pragma unroll
        for (int off = 16; off > 0; off >>= 1) {
            s0 += __shfl_xor_sync(0xffffffffu, s0, off);
            s1 += __shfl_xor_sync(0xffffffffu, s1, off);
        }
        const int lane = tid & 31;
        const int w2   = (tid >> 5) & 7;   // 8 warps in this half
        if (lane == 0) {
            sh_part[0][w2] = s0;
            sh_part[1][w2] = s1;
        }
    }
    __syncthreads();
    if (tid < 2) {
        float t = 0.f;
        #pragma unroll
        for (int i = 0; i < 8; i++) t += sh_part[tid][i];
        g_spart[((b * QQ + q0 + tid)) * 2 + chalf] = t;
    }
}

// ---------------------------------------------------------------------------
// B2: normalize weights in place. One block per (b,q): 512 blocks x 256 thr.
// ---------------------------------------------------------------------------
__global__ __launch_bounds__(256)
void norm_w(float* __restrict__ out)
{
    const int bq  = blockIdx.x;          // 0..511
    const int tid = threadIdx.x;
    const float inv = 1.f / (g_spart[bq * 2] + g_spart[bq * 2 + 1] + EPSF);
    float2* w = (float2*)&out[WOFF + (size_t)bq * CC];
    float2 v = w[tid];
    v.x *= inv; v.y *= inv;
    w[tid] = v;
}

// ---------------------------------------------------------------------------
// C: output[bq][d] = sum_c weights[bq][c] * ctx[b][c][d]
// Tiled GEMM: 64q x 32d per block, K=512, double-buffered, f32x2 FMA.
// ---------------------------------------------------------------------------
__global__ __launch_bounds__(256)
void out_gemm(const float* __restrict__ Ctx,
              const float* __restrict__ Wgt,
              float* __restrict__ out)
{
    const int blk = blockIdx.x;        // 0..127
    const int b   = blk >> 4;
    const int d0  = (blk & 15) * 32;
    const int tid = threadIdx.x;
    const int ty  = tid >> 4;
    const int tx  = tid & 15;

    __shared__ float Ws[2][16][68];
    __shared__ float Cs[2][16][34];

    const float* Wp = Wgt + (size_t)b * QQ * CC;
    const float* Cp = Ctx + (size_t)b * CC * DD;

    const int qr = tid >> 2;
    const int cg = tid & 3;
    const int cl = tid >> 4;
    const int dl = (tid & 15) * 2;

    ull acc[4] = {};

    {
        float4 w4 = *(const float4*)&Wp[qr * CC + cg * 4];
        Ws[0][cg*4+0][qr] = w4.x; Ws[0][cg*4+1][qr] = w4.y;
        Ws[0][cg*4+2][qr] = w4.z; Ws[0][cg*4+3][qr] = w4.w;
        float2 c2 = *(const float2*)&Cp[(size_t)cl * DD + d0 + dl];
        Cs[0][cl][dl] = c2.x; Cs[0][cl][dl+1] = c2.y;
    }
    __syncthreads();

    int buf = 0;
    for (int c0 = 16; c0 <= CC; c0 += 16) {
        float4 nw; float2 nc;
        const bool more = (c0 < CC);
        if (more) {
            nw = *(const float4*)&Wp[qr * CC + c0 + cg * 4];
            nc = *(const float2*)&Cp[(size_t)(c0 + cl) * DD + d0 + dl];
        }

        #pragma unroll
        for (int cc = 0; cc < 16; cc++) {
            float4 w4 = *(const float4*)&Ws[buf][cc][ty * 4];
            ull cv = *(const ull*)&Cs[buf][cc][tx * 2];
            fma2(acc[0], pack2(w4.x), cv);
            fma2(acc[1], pack2(w4.y), cv);
            fma2(acc[2], pack2(w4.z), cv);
            fma2(acc[3], pack2(w4.w), cv);
        }

        if (more) {
            const int nbuf = buf ^ 1;
            Ws[nbuf][cg*4+0][qr] = nw.x; Ws[nbuf][cg*4+1][qr] = nw.y;
            Ws[nbuf][cg*4+2][qr] = nw.z; Ws[nbuf][cg*4+3][qr] = nw.w;
            Cs[nbuf][cl][dl] = nc.x; Cs[nbuf][cl][dl+1] = nc.y;
        }
        __syncthreads();
        buf ^= 1;
    }

    #pragma unroll
    for (int i = 0; i < 4; i++) {
        float2 p = unpack2(acc[i]);
        const int q = ty * 4 + i;
        *(float2*)&out[(b * QQ + q) * DD + d0 + tx * 2] = p;
    }
}

// ---------------------------------------------------------------------------
extern "C" void kernel_launch(void* const* d_in, const int* in_sizes, int n_in,
                              void* d_out, int out_size)
{
    const float* query   = (const float*)d_in[0];
    const float* context = (const float*)d_in[1];
    const float* mask    = (const float*)d_in[2];
    const float* W_c     = (const float*)d_in[3];
    const float* b_c     = (const float*)d_in[4];
    const float* W_q     = (const float*)d_in[5];
    const float* W_o     = (const float*)d_in[6];
    const float* b_o     = (const float*)d_in[7];
    float* out = (float*)d_out;

    cudaFuncSetAttribute(tc_gemms, cudaFuncAttributeMaxDynamicSharedMemorySize,
                         TCG_SMEM);

    tc_gemms<<<144, 256, TCG_SMEM>>>(W_c, context, b_c, query, W_q);
    logits_e<<<512, 512>>>(mask, W_o, b_o, out);
    norm_w<<<512, 256>>>(out);
    out_gemm<<<128, 256>>>(context, out + WOFF, out);
}

// round 14
// speedup vs baseline: 1.1292x; 1.1292x over previous
#include <cuda_runtime.h>
#include <cuda_bf16.h>
#include <cstdint>

// Problem constants
#define BB 8
#define QQ 64
#define CC 512
#define DD 512
#define HH 256
#define EPSF 1e-5f
#define WOFF (BB * QQ * DD)

typedef unsigned long long ull;

__device__ float g_resq[BB * QQ * HH];        // [bq][h]
__device__ float g_rescT[BB * HH * CC];       // [b][h][c]

__device__ __forceinline__ float tanh_approx(float x) {
    float y;
    asm("tanh.approx.f32 %0, %1;" : "=f"(y) : "f"(x));
    return y;
}
__device__ __forceinline__ ull pack2(float x) {
    ull r; asm("mov.b64 %0, {%1, %1};" : "=l"(r) : "f"(x)); return r;
}
__device__ __forceinline__ void fma2(ull& d, ull a, ull b) {
    asm("fma.rn.f32x2 %0, %1, %2, %0;" : "+l"(d) : "l"(a), "l"(b));
}
__device__ __forceinline__ float2 unpack2(ull v) {
    float2 r; asm("mov.b64 {%0, %1}, %2;" : "=f"(r.x), "=f"(r.y) : "l"(v)); return r;
}
__device__ __forceinline__ uint32_t s2u(const void* p) {
    uint32_t a;
    asm("{ .reg .u64 t; cvta.to.shared.u64 t, %1; cvt.u32.u64 %0, t; }"
        : "=r"(a) : "l"(p));
    return a;
}
__device__ __forceinline__ void cp16(uint32_t s, const void* g) {
    asm volatile("cp.async.cg.shared.global [%0], [%1], 16;" :: "r"(s), "l"(g) : "memory");
}

#define MMA_TF32(c, a, b0, b1)                                            \
    asm volatile("mma.sync.aligned.m16n8k8.row.col.f32.tf32.tf32.f32 "    \
                 "{%0,%1,%2,%3}, {%4,%5,%6,%7}, {%8,%9}, {%0,%1,%2,%3};"  \
                 : "+f"((c)[0]), "+f"((c)[1]), "+f"((c)[2]), "+f"((c)[3]) \
                 : "r"((a)[0]), "r"((a)[1]), "r"((a)[2]), "r"((a)[3]),    \
                   "r"(b0), "r"(b1))

// ---- tc_gemms tiling: K-tile 64, 3 stages ----
#define LDA 72
#define ATILE_U (128 * LDA)
#define BTILE_U (64 * LDA)
#define STAGE_U (ATILE_U + BTILE_U)
#define NSTAGE 3
#define TCG_SMEM (NSTAGE * STAGE_U * 4)   // 165888 B

// ---------------------------------------------------------------------------
// A: tf32 mma.sync GEMMs, cp.async 3-stage pipeline, K-tile 64. 144 blocks.
// ---------------------------------------------------------------------------
__global__ __launch_bounds__(256, 1)
void tc_gemms(const float* __restrict__ Wc,
              const float* __restrict__ Ctx,
              const float* __restrict__ bc,
              const float* __restrict__ Qm,
              const float* __restrict__ Wq)
{
    extern __shared__ uint32_t smem[];
    const uint32_t smem_b = s2u(smem);

    const int tid  = threadIdx.x;
    const int wid  = tid >> 5;
    const int lane = tid & 31;
    const int g    = lane >> 2;
    const int tg   = lane & 3;

    const int mbase = (wid & 3) * 32;
    const int nbase = (wid >> 2) * 32;

    const float *Ap, *Bp;
    const float* biasp = nullptr;
    float* outp;
    int ldo;
    const int blk = blockIdx.x;
    if (blk < 128) {
        const int b  = blk >> 4;
        const int ht = (blk >> 3) & 1;
        const int ct = blk & 7;
        Ap    = Wc + (size_t)(ht * 128) * DD;
        Bp    = Ctx + (size_t)b * CC * DD + (size_t)(ct * 64) * DD;
        outp  = g_rescT + (size_t)b * HH * CC + (size_t)(ht * 128) * CC + ct * 64;
        ldo   = CC;
        biasp = bc + ht * 128;
    } else {
        const int blk2 = blk - 128;
        const int mt = blk2 >> 2;
        const int nt = blk2 & 3;
        Ap   = Qm + (size_t)(mt * 128) * DD;
        Bp   = Wq + (size_t)(nt * 64) * DD;
        outp = g_resq + (size_t)(mt * 128) * HH + nt * 64;
        ldo  = HH;
    }

    int am[8], ak[8], bm[4], bk[4];
    #pragma unroll
    for (int i = 0; i < 8; i++) {
        const int f = tid + (i << 8);
        am[i] = f >> 4;
        ak[i] = (f & 15) << 2;
    }
    #pragma unroll
    for (int i = 0; i < 4; i++) {
        const int f = tid + (i << 8);
        bm[i] = f >> 4;
        bk[i] = (f & 15) << 2;
    }

    auto issue_stage = [&](int buf, int kt) {
        const uint32_t base = smem_b + buf * (STAGE_U * 4);
        #pragma unroll
        for (int i = 0; i < 8; i++)
            cp16(base + (am[i] * LDA + ak[i]) * 4,
                 Ap + (size_t)am[i] * DD + kt + ak[i]);
        #pragma unroll
        for (int i = 0; i < 4; i++)
            cp16(base + (ATILE_U + bm[i] * LDA + bk[i]) * 4,
                 Bp + (size_t)bm[i] * DD + kt + bk[i]);
        asm volatile("cp.async.commit_group;" ::: "memory");
    };

    float acc[2][4][4] = {};

    issue_stage(0, 0);
    issue_stage(1, 64);

    const int foff = 2 * tg;

    #pragma unroll 1
    for (int t = 0; t < 8; t++) {
        if (t < 6) {
            asm volatile("cp.async.wait_group 1;" ::: "memory");
        } else {
            asm volatile("cp.async.wait_group 0;" ::: "memory");
        }
        __syncthreads();

        if (t < 6) issue_stage((t + 2) % NSTAGE, (t + 2) * 64);

        const uint32_t* A_s = smem + (t % NSTAGE) * STAGE_U;
        const uint32_t* B_s = A_s + ATILE_U;
        #pragma unroll
        for (int ks = 0; ks < 8; ks++) {
            const int kc = ks * 8 + foff;
            uint32_t a[2][4];
            #pragma unroll
            for (int mt = 0; mt < 2; mt++) {
                const int rbase = (mbase + mt * 16 + g) * LDA + kc;
                const uint2 lo = *(const uint2*)&A_s[rbase];
                const uint2 hi = *(const uint2*)&A_s[rbase + 8 * LDA];
                a[mt][0] = lo.x; a[mt][2] = lo.y;
                a[mt][1] = hi.x; a[mt][3] = hi.y;
            }
            #pragma unroll
            for (int nt = 0; nt < 4; nt++) {
                const int bbase = (nbase + nt * 8 + g) * LDA + kc;
                const uint2 bv = *(const uint2*)&B_s[bbase];
                MMA_TF32(acc[0][nt], a[0], bv.x, bv.y);
                MMA_TF32(acc[1][nt], a[1], bv.x, bv.y);
            }
        }
    }

    #pragma unroll
    for (int mt = 0; mt < 2; mt++) {
        const int row0 = mbase + mt * 16 + g;
        const int row1 = row0 + 8;
        const float bi0 = biasp ? biasp[row0] : 0.f;
        const float bi1 = biasp ? biasp[row1] : 0.f;
        #pragma unroll
        for (int nt = 0; nt < 4; nt++) {
            const int col = nbase + nt * 8 + tg * 2;
            float2 o0; o0.x = acc[mt][nt][0] + bi0; o0.y = acc[mt][nt][1] + bi0;
            float2 o1; o1.x = acc[mt][nt][2] + bi1; o1.y = acc[mt][nt][3] + bi1;
            *(float2*)(outp + (size_t)row0 * ldo + col) = o0;
            *(float2*)(outp + (size_t)row1 * ldo + col) = o1;
        }
    }
}

// ---------------------------------------------------------------------------
// B: logits (tanh over H) + softmax; writes weights to out[WOFF..].
// R10 best-measured version: q-tile 4, grid 128, 1024 threads, h-split halves.
// ---------------------------------------------------------------------------
__global__ __launch_bounds__(1024)
void logits_softmax(const float* __restrict__ Maskp,
                    const float* __restrict__ Wo,
                    const float* __restrict__ bo_p,
                    float* __restrict__ out)
{
    const int blk  = blockIdx.x;       // 0..127
    const int b    = blk >> 4;
    const int q0   = (blk & 15) * 4;
    const int tid  = threadIdx.x;
    const int c    = tid & 511;
    const int half = tid >> 9;

    __shared__ float4 sh_rq[HH];
    __shared__ float  sh_wo[HH];
    __shared__ float4 sh_acc[CC];
    __shared__ float  sh_part[4][16];
    __shared__ float  sh_tot[4];

    if (tid < HH) {
        float4 r;
        r.x = g_resq[(b * QQ + q0 + 0) * HH + tid];
        r.y = g_resq[(b * QQ + q0 + 1) * HH + tid];
        r.z = g_resq[(b * QQ + q0 + 2) * HH + tid];
        r.w = g_resq[(b * QQ + q0 + 3) * HH + tid];
        sh_rq[tid] = r;
        sh_wo[tid] = Wo[tid];
    }
    __syncthreads();

    float a0 = 0.f, a1 = 0.f, a2 = 0.f, a3 = 0.f;
    {
        const int hbase = half << 7;
        const float* rc = g_rescT + (size_t)b * HH * CC + (size_t)hbase * CC + c;
        #pragma unroll 8
        for (int h = 0; h < 128; h++) {
            const float  a  = rc[(size_t)h * CC];
            const float4 rq = sh_rq[hbase + h];
            const float  w  = sh_wo[hbase + h];
            a0 += w * tanh_approx(a + rq.x);
            a1 += w * tanh_approx(a + rq.y);
            a2 += w * tanh_approx(a + rq.z);
            a3 += w * tanh_approx(a + rq.w);
        }
    }
    if (half == 0) {
        sh_acc[c] = make_float4(a0, a1, a2, a3);
    }
    __syncthreads();

    float e0, e1, e2, e3;
    if (half == 1) {
        const float4 p = sh_acc[c];
        const float bo = __ldg(bo_p);
        const float m  = Maskp[b * CC + c];
        e0 = m * __expf(a0 + p.x + bo);
        e1 = m * __expf(a1 + p.y + bo);
        e2 = m * __expf(a2 + p.z + bo);
        e3 = m * __expf(a3 + p.w + bo);

        float s0 = e0, s1 = e1, s2 = e2, s3 = e3;
        #pragma unroll
        for (int off = 16; off > 0; off >>= 1) {
            s0 += __shfl_xor_sync(0xffffffffu, s0, off);
            s1 += __shfl_xor_sync(0xffffffffu, s1, off);
            s2 += __shfl_xor_sync(0xffffffffu, s2, off);
            s3 += __shfl_xor_sync(0xffffffffu, s3, off);
        }
        const int lane = tid & 31, w2 = (tid >> 5) & 15;
        if (lane == 0) {
            sh_part[0][w2] = s0; sh_part[1][w2] = s1;
            sh_part[2][w2] = s2; sh_part[3][w2] = s3;
        }
    }
    __syncthreads();
    if (tid < 4) {
        float t = 0.f;
        #pragma unroll
        for (int i = 0; i < 16; i++) t += sh_part[tid][i];
        sh_tot[tid] = 1.f / (t + EPSF);
    }
    __syncthreads();

    if (half == 1) {
        out[WOFF + (b * QQ + q0 + 0) * CC + c] = e0 * sh_tot[0];
        out[WOFF + (b * QQ + q0 + 1) * CC + c] = e1 * sh_tot[1];
        out[WOFF + (b * QQ + q0 + 2) * CC + c] = e2 * sh_tot[2];
        out[WOFF + (b * QQ + q0 + 3) * CC + c] = e3 * sh_tot[3];
    }
}

// ---------------------------------------------------------------------------
// C: output[bq][d] = sum_c weights[bq][c] * ctx[b][c][d]
// cp.async 3-stage pipeline, K(=c)-tile 64 (8 barriers). 128 blocks x 256 thr.
// Block tile 64q x 32d. Weights staged in NATIVE [q][c] layout: the per-k
// column reads are warp-broadcast LDS (all 16 tx share one address).
// fp32 f32x2 math (bit-exact vs reference accumulation order).
// ---------------------------------------------------------------------------
#define OG_LDW 68                    // weights row: 64 c + 4 pad (u32)
#define OG_LDC 36                    // ctx row: 32 d + 4 pad (u32)
#define OG_WS_U (64 * OG_LDW)        // 4352 u32
#define OG_CS_U (64 * OG_LDC)        // 2304 u32
#define OG_STAGE_U (OG_WS_U + OG_CS_U) // 6656 u32
#define OG_SMEM (NSTAGE * OG_STAGE_U * 4)  // 79872 B

__global__ __launch_bounds__(256, 1)
void out_gemm(const float* __restrict__ Ctx,
              const float* __restrict__ Wgt,   // = out + WOFF
              float* __restrict__ out)
{
    extern __shared__ uint32_t smem[];
    const uint32_t smem_b = s2u(smem);

    const int blk = blockIdx.x;        // 0..127
    const int b   = blk >> 4;
    const int d0  = (blk & 15) * 32;
    const int tid = threadIdx.x;
    const int ty  = tid >> 4;          // q group (4 rows)
    const int tx  = tid & 15;          // d pair

    const float* Wp = Wgt + (size_t)b * QQ * CC;
    const float* Cp = Ctx + (size_t)b * CC * DD + d0;

    // staging coords: Ws 64q x 64c = 1024 f4 (4/thread); Cs 64c x 32d = 512 f4 (2/thread)
    int wq[4], wc[4], cc_[2], cd[2];
    #pragma unroll
    for (int i = 0; i < 4; i++) {
        const int f = tid + (i << 8);
        wq[i] = f >> 4;                // 0..63
        wc[i] = (f & 15) << 2;         // 0..60
    }
    #pragma unroll
    for (int i = 0; i < 2; i++) {
        const int f = tid + (i << 8);
        cc_[i] = f >> 3;               // 0..63
        cd[i]  = (f & 7) << 2;         // 0..28
    }

    auto issue_stage = [&](int buf, int kt) {
        const uint32_t base = smem_b + buf * (OG_STAGE_U * 4);
        #pragma unroll
        for (int i = 0; i < 4; i++)
            cp16(base + (wq[i] * OG_LDW + wc[i]) * 4,
                 Wp + (size_t)wq[i] * CC + kt + wc[i]);
        #pragma unroll
        for (int i = 0; i < 2; i++)
            cp16(base + (OG_WS_U + cc_[i] * OG_LDC + cd[i]) * 4,
                 Cp + (size_t)(kt + cc_[i]) * DD + cd[i]);
        asm volatile("cp.async.commit_group;" ::: "memory");
    };

    ull acc[4] = {};

    issue_stage(0, 0);
    issue_stage(1, 64);

    #pragma unroll 1
    for (int t = 0; t < 8; t++) {
        if (t < 6) {
            asm volatile("cp.async.wait_group 1;" ::: "memory");
        } else {
            asm volatile("cp.async.wait_group 0;" ::: "memory");
        }
        __syncthreads();

        if (t < 6) issue_stage((t + 2) % NSTAGE, (t + 2) * 64);

        const float* W_s = (const float*)(smem + (t % NSTAGE) * OG_STAGE_U);
        const float* C_s = W_s + OG_WS_U;
        #pragma unroll 8
        for (int cc = 0; cc < 64; cc++) {
            const ull cv = *(const ull*)&C_s[cc * OG_LDC + tx * 2];
            const float w0 = W_s[(ty * 4 + 0) * OG_LDW + cc];
            const float w1 = W_s[(ty * 4 + 1) * OG_LDW + cc];
            const float w2 = W_s[(ty * 4 + 2) * OG_LDW + cc];
            const float w3 = W_s[(ty * 4 + 3) * OG_LDW + cc];
            fma2(acc[0], pack2(w0), cv);
            fma2(acc[1], pack2(w1), cv);
            fma2(acc[2], pack2(w2), cv);
            fma2(acc[3], pack2(w3), cv);
        }
    }

    #pragma unroll
    for (int i = 0; i < 4; i++) {
        float2 p = unpack2(acc[i]);
        const int q = ty * 4 + i;
        *(float2*)&out[(b * QQ + q) * DD + d0 + tx * 2] = p;
    }
}

// ---------------------------------------------------------------------------
extern "C" void kernel_launch(void* const* d_in, const int* in_sizes, int n_in,
                              void* d_out, int out_size)
{
    const float* query   = (const float*)d_in[0];
    const float* context = (const float*)d_in[1];
    const float* mask    = (const float*)d_in[2];
    const float* W_c     = (const float*)d_in[3];
    const float* b_c     = (const float*)d_in[4];
    const float* W_q     = (const float*)d_in[5];
    const float* W_o     = (const float*)d_in[6];
    const float* b_o     = (const float*)d_in[7];
    float* out = (float*)d_out;

    cudaFuncSetAttribute(tc_gemms, cudaFuncAttributeMaxDynamicSharedMemorySize,
                         TCG_SMEM);
    cudaFuncSetAttribute(out_gemm, cudaFuncAttributeMaxDynamicSharedMemorySize,
                         OG_SMEM);

    tc_gemms<<<144, 256, TCG_SMEM>>>(W_c, context, b_c, query, W_q);
    logits_softmax<<<128, 1024>>>(mask, W_o, b_o, out);
    out_gemm<<<128, 256, OG_SMEM>>>(context, out + WOFF, out);
}